// round 13
// baseline (speedup 1.0000x reference)
#include <cuda_runtime.h>
#include <cuda_fp16.h>
#include <math.h>

#define SEQ    4096
#define DMODEL 1024
#define HEADS  8
#define ZIPD   256
#define DH     32      // ZIP / HEADS
#define DV     128     // DMODEL / HEADS

// ---------------- scratch (no allocation allowed) ----------------
__device__ __align__(16) float  g_Q[SEQ * ZIPD];                 // 4 MB   fp32 Q-proj
__device__ __align__(16) __half g_Kh[SEQ * ZIPD];                // 2 MB   K-proj fp16
__device__ __align__(16) __half g_Th[SEQ * ZIPD];                // 2 MB   T (v@wvr) hi
__device__ __align__(16) __half g_Tl[SEQ * ZIPD];                // 2 MB   T lo
__device__ __align__(16) __half g_V[SEQ * DMODEL];               // 8 MB   value, fp16 row-major
__device__ __align__(16) __half g_Wh[3 * ZIPD * DMODEL];         // 1.5 MB wq,wk,wvr hi
__device__ __align__(16) __half g_Wl[3 * ZIPD * DMODEL];         // 1.5 MB lo
__device__ __align__(16) __half g_WVh[DMODEL * ZIPD];            // 0.5 MB wvl hi
__device__ __align__(16) __half g_WVl[DMODEL * ZIPD];            // 0.5 MB lo
__device__ int g_KmaxI[HEADS];                                   // max ||k||^2 per head (float bits; idempotent)

__device__ __forceinline__ unsigned h2u(__half2 h) { return *reinterpret_cast<unsigned*>(&h); }

// split float4 -> hi half4 + lo half4
__device__ __forceinline__ void split4(float4 v, uint2& uh, uint2& ul)
{
    __half h0 = __float2half_rn(v.x), h1 = __float2half_rn(v.y);
    __half h2 = __float2half_rn(v.z), h3 = __float2half_rn(v.w);
    uh.x = h2u(__halves2half2(h0, h1));
    uh.y = h2u(__halves2half2(h2, h3));
    ul.x = h2u(__floats2half2_rn(v.x - __half2float(h0), v.y - __half2float(h1)));
    ul.y = h2u(__floats2half2_rn(v.z - __half2float(h2), v.w - __half2float(h3)));
}

// ---------------- weight conversion ----------------
__global__ void conv_w_kernel(const float* __restrict__ wq,
                              const float* __restrict__ wk,
                              const float* __restrict__ wvr,
                              const float* __restrict__ wvl)
{
    int i = blockIdx.x * 256 + threadIdx.x;              // float4 index
    const int WSZ = ZIPD * DMODEL / 4;                   // 65536
    uint2 uh, ul;
    if (i < 3 * WSZ) {
        int m = i / WSZ, off = i % WSZ;
        const float* src = (m == 0) ? wq : (m == 1) ? wk : wvr;
        float4 x = ((const float4*)src)[off];
        split4(x, uh, ul);
        ((uint2*)g_Wh)[i] = uh;
        ((uint2*)g_Wl)[i] = ul;
    } else {
        int off = i - 3 * WSZ;
        float4 x = ((const float4*)wvl)[off];
        split4(x, uh, ul);
        ((uint2*)g_WVh)[off] = uh;
        ((uint2*)g_WVl)[off] = ul;
    }
}

// ---------------- k-norm max kernel ----------------
__global__ void knorm_kernel()
{
    __shared__ float red[256];
    const int h   = blockIdx.y;
    const int key = blockIdx.x * 256 + threadIdx.x;
    const uint4* kp = (const uint4*)(g_Kh + (size_t)key * ZIPD + h * DH);
    float s = 0.f;
#pragma unroll
    for (int i = 0; i < 4; i++) {
        uint4 u = kp[i];
        unsigned w[4] = {u.x, u.y, u.z, u.w};
#pragma unroll
        for (int j = 0; j < 4; j++) {
            __half2 hv = *reinterpret_cast<__half2*>(&w[j]);
            float2 f = __half22float2(hv);
            s = fmaf(f.x, f.x, s);
            s = fmaf(f.y, f.y, s);
        }
    }
    red[threadIdx.x] = s;
    __syncthreads();
#pragma unroll
    for (int st = 128; st > 0; st >>= 1) {
        if (threadIdx.x < st) red[threadIdx.x] = fmaxf(red[threadIdx.x], red[threadIdx.x + st]);
        __syncthreads();
    }
    if (threadIdx.x == 0)
        atomicMax(&g_KmaxI[h], __float_as_int(red[0]));
}

// ---------------- MMA helpers ----------------
__device__ __forceinline__ void mma16816(float& c0, float& c1, float& c2, float& c3,
                                         unsigned a0, unsigned a1, unsigned a2, unsigned a3,
                                         unsigned b0, unsigned b1)
{
    asm volatile("mma.sync.aligned.m16n8k16.row.col.f32.f16.f16.f32 "
                 "{%0,%1,%2,%3},{%4,%5,%6,%7},{%8,%9},{%0,%1,%2,%3};"
                 : "+f"(c0), "+f"(c1), "+f"(c2), "+f"(c3)
                 : "r"(a0), "r"(a1), "r"(a2), "r"(a3), "r"(b0), "r"(b1));
}

#define LDSM4(R0, R1, R2, R3, ADDR) \
    asm volatile("ldmatrix.sync.aligned.m8n8.x4.shared.b16 {%0,%1,%2,%3}, [%4];" \
                 : "=r"(R0), "=r"(R1), "=r"(R2), "=r"(R3) : "r"(ADDR))

#define LDSM4T(R0, R1, R2, R3, ADDR) \
    asm volatile("ldmatrix.sync.aligned.m8n8.x4.trans.shared.b16 {%0,%1,%2,%3}, [%4];" \
                 : "=r"(R0), "=r"(R1), "=r"(R2), "=r"(R3) : "r"(ADDR))

#define CP16(DST, SRC) \
    asm volatile("cp.async.cg.shared.global [%0], [%1], 16;" :: "r"(DST), "l"(SRC))

// ---------------- GEMM smem layout ----------------
#define GASTR 40
#define G_AL  (128 * GASTR)
#define G_WH  (2 * 128 * GASTR)
#define G_WL  (2 * 128 * GASTR + 64 * GASTR)
#define G_STG (2 * 128 * GASTR + 2 * 64 * GASTR)   // 15360 halves = 30720 B

// ---------------- gemm1: fused fp32->hi/lo split + MMA ----------------
// mode: 0 -> g_Q fp32; 1 -> g_Kh fp16; 2 -> g_Th/g_Tl
// modes 0/1: 2-pass split (hh+hl) — their outputs get fp16-rounded by attention anyway.
// mode 2:    3-pass (hh+hl+lh) — feeds V directly.
__global__ void __launch_bounds__(128, 3)
gemm1_kernel(const float* __restrict__ qin, const float* __restrict__ kin,
             const float* __restrict__ vin,
             const float* __restrict__ bq, const float* __restrict__ bk,
             const float* __restrict__ bvr)
{
    extern __shared__ __align__(16) __half gsm[];
    const unsigned smem_base = (unsigned)__cvta_generic_to_shared(gsm);

    const int mode = blockIdx.z;
    const float* A    = (mode == 0) ? qin : (mode == 1) ? kin : vin;
    const __half* Wh  = g_Wh + (size_t)mode * ZIPD * DMODEL;
    const __half* Wl  = g_Wl + (size_t)mode * ZIPD * DMODEL;
    const float* bias = (mode == 0) ? bq : (mode == 1) ? bk : bvr;
    const int K = DMODEL;
    const bool lh_pass = (mode == 2);

    const int tid  = threadIdx.x;
    const int wid  = tid >> 5;
    const int lane = tid & 31;
    const int grp  = lane >> 2;
    const int t    = lane & 3;
    const int mi   = lane >> 3;
    const int r8   = lane & 7;
    const int m0   = blockIdx.y * 128;
    const int n0   = blockIdx.x * 64;

    const unsigned a_lofs = (unsigned)(((((mi & 1) * 8 + r8) * GASTR) + (mi >> 1) * 8) * 2);
    const unsigned w_lofs = (unsigned)((r8 * GASTR + (mi >> 1) * 16 + (mi & 1) * 8) * 2);

    float o[2][8][4];
#pragma unroll
    for (int mf = 0; mf < 2; mf++)
#pragma unroll
        for (int nf = 0; nf < 8; nf++)
#pragma unroll
            for (int r = 0; r < 4; r++) o[mf][nf][r] = 0.f;

    float4 areg[8];
    auto ldA = [&](int k0) {
#pragma unroll
        for (int it = 0; it < 8; it++) {
            int c = it * 128 + tid;
            int row = c >> 3, ch = c & 7;
            areg[it] = *(const float4*)(A + (size_t)(m0 + row) * K + k0 + ch * 4);
        }
    };
    auto stsA = [&](int stage) {
#pragma unroll
        for (int it = 0; it < 8; it++) {
            int c = it * 128 + tid;
            int row = c >> 3, ch = c & 7;
            uint2 uh, ul;
            split4(areg[it], uh, ul);
            *(uint2*)(gsm + stage * G_STG + row * GASTR + ch * 4) = uh;
            if (lh_pass)
                *(uint2*)(gsm + stage * G_STG + G_AL + row * GASTR + ch * 4) = ul;
        }
    };
    auto fillW = [&](int stage, int k0) {
#pragma unroll
        for (int it = 0; it < 4; it++) {
            int c = it * 128 + tid;
            int arr = c >> 8, cc = c & 255;
            int row = cc >> 2, ch = cc & 3;
            const __half* src = (arr ? Wl : Wh) + (size_t)(n0 + row) * K + k0 + ch * 8;
            unsigned dst = smem_base +
                (unsigned)((stage * G_STG + (arr ? G_WL : G_WH) + row * GASTR + ch * 8) * 2);
            CP16(dst, src);
        }
    };

    const int NIT = K / 32;   // 32
    ldA(0);
    stsA(0);
    fillW(0, 0);
    asm volatile("cp.async.commit_group;");
    ldA(32);

    for (int it2 = 0; it2 < NIT; it2++) {
        asm volatile("cp.async.wait_group 0;");
        __syncthreads();
        if (it2 + 1 < NIT) {
            stsA((it2 + 1) & 1);
            fillW((it2 + 1) & 1, (it2 + 1) * 32);
            asm volatile("cp.async.commit_group;");
            if (it2 + 2 < NIT) ldA((it2 + 2) * 32);
        }
        unsigned sb = smem_base + (unsigned)((it2 & 1) * G_STG * 2);

        unsigned ah[2][2][4], al[2][2][4];
#pragma unroll
        for (int mf = 0; mf < 2; mf++)
#pragma unroll
            for (int kk = 0; kk < 2; kk++) {
                unsigned base = (unsigned)(((wid * 32 + mf * 16) * GASTR + kk * 16) * 2);
                LDSM4(ah[mf][kk][0], ah[mf][kk][1], ah[mf][kk][2], ah[mf][kk][3],
                      sb + base + a_lofs);
                if (lh_pass)
                    LDSM4(al[mf][kk][0], al[mf][kk][1], al[mf][kk][2], al[mf][kk][3],
                          sb + (unsigned)(G_AL * 2) + base + a_lofs);
            }

#pragma unroll
        for (int nf = 0; nf < 8; nf++) {
            unsigned wh[4], wl[4];
            unsigned wbase = (unsigned)((nf * 8 * GASTR) * 2);
            LDSM4(wh[0], wh[1], wh[2], wh[3], sb + (unsigned)(G_WH * 2) + wbase + w_lofs);
            LDSM4(wl[0], wl[1], wl[2], wl[3], sb + (unsigned)(G_WL * 2) + wbase + w_lofs);
#pragma unroll
            for (int mf = 0; mf < 2; mf++)
#pragma unroll
                for (int kk = 0; kk < 2; kk++) {
                    mma16816(o[mf][nf][0], o[mf][nf][1], o[mf][nf][2], o[mf][nf][3],
                             ah[mf][kk][0], ah[mf][kk][1], ah[mf][kk][2], ah[mf][kk][3],
                             wh[2 * kk], wh[2 * kk + 1]);
                    mma16816(o[mf][nf][0], o[mf][nf][1], o[mf][nf][2], o[mf][nf][3],
                             ah[mf][kk][0], ah[mf][kk][1], ah[mf][kk][2], ah[mf][kk][3],
                             wl[2 * kk], wl[2 * kk + 1]);
                    if (lh_pass)
                        mma16816(o[mf][nf][0], o[mf][nf][1], o[mf][nf][2], o[mf][nf][3],
                                 al[mf][kk][0], al[mf][kk][1], al[mf][kk][2], al[mf][kk][3],
                                 wh[2 * kk], wh[2 * kk + 1]);
                }
        }
    }

    // ---- epilogue ----
#pragma unroll
    for (int mf = 0; mf < 2; mf++) {
        int row0 = m0 + wid * 32 + mf * 16 + grp;
        int row1 = row0 + 8;
#pragma unroll
        for (int nf = 0; nf < 8; nf++) {
            int col = n0 + nf * 8 + 2 * t;
            float b0 = bias[col], b1 = bias[col + 1];
            float x0 = o[mf][nf][0] + b0, x1 = o[mf][nf][1] + b1;
            float x2 = o[mf][nf][2] + b0, x3 = o[mf][nf][3] + b1;
            if (mode == 0) {
                *(float2*)(g_Q + (size_t)row0 * ZIPD + col) = make_float2(x0, x1);
                *(float2*)(g_Q + (size_t)row1 * ZIPD + col) = make_float2(x2, x3);
            } else if (mode == 1) {
                *(__half2*)(g_Kh + (size_t)row0 * ZIPD + col) = __floats2half2_rn(x0, x1);
                *(__half2*)(g_Kh + (size_t)row1 * ZIPD + col) = __floats2half2_rn(x2, x3);
            } else {
                __half h0 = __float2half_rn(x0), h1 = __float2half_rn(x1);
                __half h2 = __float2half_rn(x2), h3 = __float2half_rn(x3);
                *(__half2*)(g_Th + (size_t)row0 * ZIPD + col) = __halves2half2(h0, h1);
                *(__half2*)(g_Th + (size_t)row1 * ZIPD + col) = __halves2half2(h2, h3);
                *(__half2*)(g_Tl + (size_t)row0 * ZIPD + col) =
                    __floats2half2_rn(x0 - __half2float(h0), x1 - __half2float(h1));
                *(__half2*)(g_Tl + (size_t)row1 * ZIPD + col) =
                    __floats2half2_rn(x2 - __half2float(h2), x3 - __half2float(h3));
            }
        }
    }
}

// ---------------- gemm2: T @ wvl^T (3-pass split) ----------------
__global__ void __launch_bounds__(128, 2)
gemm2_kernel(const float* __restrict__ bvl)
{
    extern __shared__ __align__(16) __half gsm[];
    const unsigned smem_base = (unsigned)__cvta_generic_to_shared(gsm);

    const __half* Ah = g_Th;
    const __half* Al = g_Tl;
    const __half* Wh = g_WVh;
    const __half* Wl = g_WVl;
    const float* bias = bvl;
    const int K = ZIPD;

    const int tid  = threadIdx.x;
    const int wid  = tid >> 5;
    const int lane = tid & 31;
    const int grp  = lane >> 2;
    const int t    = lane & 3;
    const int mi   = lane >> 3;
    const int r8   = lane & 7;
    const int m0   = blockIdx.y * 128;
    const int n0   = blockIdx.x * 64;

    const unsigned a_lofs = (unsigned)(((((mi & 1) * 8 + r8) * GASTR) + (mi >> 1) * 8) * 2);
    const unsigned w_lofs = (unsigned)((r8 * GASTR + (mi >> 1) * 16 + (mi & 1) * 8) * 2);

    float o[2][8][4];
#pragma unroll
    for (int mf = 0; mf < 2; mf++)
#pragma unroll
        for (int nf = 0; nf < 8; nf++)
#pragma unroll
            for (int r = 0; r < 4; r++) o[mf][nf][r] = 0.f;

    auto fill = [&](int stage, int k0) {
        unsigned sb = smem_base + (unsigned)(stage * G_STG * 2);
#pragma unroll
        for (int it = 0; it < 8; it++) {
            int c = it * 128 + tid;
            int arr = c >> 9, cc = c & 511;
            int row = cc >> 2, ch = cc & 3;
            const __half* src = (arr ? Al : Ah) + (size_t)(m0 + row) * K + k0 + ch * 8;
            unsigned dst = sb + (unsigned)(((arr ? G_AL : 0) + row * GASTR + ch * 8) * 2);
            CP16(dst, src);
        }
#pragma unroll
        for (int it = 0; it < 4; it++) {
            int c = it * 128 + tid;
            int arr = c >> 8, cc = c & 255;
            int row = cc >> 2, ch = cc & 3;
            const __half* src = (arr ? Wl : Wh) + (size_t)(n0 + row) * K + k0 + ch * 8;
            unsigned dst = sb + (unsigned)(((arr ? G_WL : G_WH) + row * GASTR + ch * 8) * 2);
            CP16(dst, src);
        }
    };

    const int NIT = K / 32;
    fill(0, 0);
    asm volatile("cp.async.commit_group;");

    for (int it2 = 0; it2 < NIT; it2++) {
        asm volatile("cp.async.wait_group 0;");
        __syncthreads();
        if (it2 + 1 < NIT) {
            fill((it2 + 1) & 1, (it2 + 1) * 32);
            asm volatile("cp.async.commit_group;");
        }
        unsigned sb = smem_base + (unsigned)((it2 & 1) * G_STG * 2);

        unsigned ah[2][2][4], al[2][2][4];
#pragma unroll
        for (int mf = 0; mf < 2; mf++)
#pragma unroll
            for (int kk = 0; kk < 2; kk++) {
                unsigned base = (unsigned)(((wid * 32 + mf * 16) * GASTR + kk * 16) * 2);
                LDSM4(ah[mf][kk][0], ah[mf][kk][1], ah[mf][kk][2], ah[mf][kk][3],
                      sb + base + a_lofs);
                LDSM4(al[mf][kk][0], al[mf][kk][1], al[mf][kk][2], al[mf][kk][3],
                      sb + (unsigned)(G_AL * 2) + base + a_lofs);
            }

#pragma unroll
        for (int nf = 0; nf < 8; nf++) {
            unsigned wh[4], wl[4];
            unsigned wbase = (unsigned)((nf * 8 * GASTR) * 2);
            LDSM4(wh[0], wh[1], wh[2], wh[3], sb + (unsigned)(G_WH * 2) + wbase + w_lofs);
            LDSM4(wl[0], wl[1], wl[2], wl[3], sb + (unsigned)(G_WL * 2) + wbase + w_lofs);
#pragma unroll
            for (int mf = 0; mf < 2; mf++)
#pragma unroll
                for (int kk = 0; kk < 2; kk++) {
                    mma16816(o[mf][nf][0], o[mf][nf][1], o[mf][nf][2], o[mf][nf][3],
                             ah[mf][kk][0], ah[mf][kk][1], ah[mf][kk][2], ah[mf][kk][3],
                             wh[2 * kk], wh[2 * kk + 1]);
                    mma16816(o[mf][nf][0], o[mf][nf][1], o[mf][nf][2], o[mf][nf][3],
                             ah[mf][kk][0], ah[mf][kk][1], ah[mf][kk][2], ah[mf][kk][3],
                             wl[2 * kk], wl[2 * kk + 1]);
                    mma16816(o[mf][nf][0], o[mf][nf][1], o[mf][nf][2], o[mf][nf][3],
                             al[mf][kk][0], al[mf][kk][1], al[mf][kk][2], al[mf][kk][3],
                             wh[2 * kk], wh[2 * kk + 1]);
                }
        }
    }

    // epilogue: fp16 V row-major
#pragma unroll
    for (int mf = 0; mf < 2; mf++) {
        int row0 = m0 + wid * 32 + mf * 16 + grp;
        int row1 = row0 + 8;
#pragma unroll
        for (int nf = 0; nf < 8; nf++) {
            int col = n0 + nf * 8 + 2 * t;
            float b0 = bias[col], b1 = bias[col + 1];
            *(__half2*)(g_V + (size_t)row0 * DMODEL + col) =
                __floats2half2_rn(o[mf][nf][0] + b0, o[mf][nf][1] + b1);
            *(__half2*)(g_V + (size_t)row1 * DMODEL + col) =
                __floats2half2_rn(o[mf][nf][2] + b0, o[mf][nf][3] + b1);
        }
    }
}

// ---------------- fp16-MMA flash attention (static bound, f16x2 exp, ones-MMA l) ----------------
#define KSTR 40    // halves: 80 B row stride -> conflict-free LDSM
#define VSTR2 136  // halves: 272 B row stride ([k][n] tile) -> conflict-free trans LDSM

#define STG_V    (128 * KSTR)
#define STG_SIZE (128 * KSTR + 128 * VSTR2)   // 22528 halves = 45056 B
#define NSTAGE   2
#define NTILE    (SEQ / 128)                  // 32

__global__ void __launch_bounds__(128, 2)
attn_kernel(float* __restrict__ O)
{
    extern __shared__ __align__(16) __half sm[];

    const int tid  = threadIdx.x;
    const int wid  = tid >> 5;
    const int lane = tid & 31;
    const int grp  = lane >> 2;
    const int t    = lane & 3;
    const int h    = blockIdx.y;
    const int q0   = blockIdx.x * 64;
    const int qr   = q0 + wid * 16;

    const unsigned smem_base = (unsigned)__cvta_generic_to_shared(sm);
    const unsigned ONES = 0x3C003C00u;   // half2(1,1)

    const int mi = lane >> 3;
    const int r8 = lane & 7;
    const unsigned k_lofs = (unsigned)((r8 * KSTR + (mi >> 1) * 16 + (mi & 1) * 8) * 2);
    const unsigned v_lofs = (unsigned)(((((mi & 1) * 8 + r8) * VSTR2) + (mi >> 1) * 8) * 2);

    // ---- Q fragments (fp16, pre-scaled by log2(e)), plus per-row ||q||^2 ----
    const float L2E = 1.44269504088896341f;
    unsigned qh[2][4];
    float qs0 = 0.f, qs1 = 0.f;
#pragma unroll
    for (int c = 0; c < 2; c++) {
        int cb = h * DH + 16 * c;
        const float* r0p = g_Q + (size_t)(qr + grp) * ZIPD + cb;
        const float* r1p = g_Q + (size_t)(qr + grp + 8) * ZIPD + cb;
        float2 xs[4];
        xs[0] = *(const float2*)(r0p + 2 * t);
        xs[1] = *(const float2*)(r1p + 2 * t);
        xs[2] = *(const float2*)(r0p + 8 + 2 * t);
        xs[3] = *(const float2*)(r1p + 8 + 2 * t);
        qs0 = fmaf(xs[0].x, xs[0].x, qs0); qs0 = fmaf(xs[0].y, xs[0].y, qs0);
        qs0 = fmaf(xs[2].x, xs[2].x, qs0); qs0 = fmaf(xs[2].y, xs[2].y, qs0);
        qs1 = fmaf(xs[1].x, xs[1].x, qs1); qs1 = fmaf(xs[1].y, xs[1].y, qs1);
        qs1 = fmaf(xs[3].x, xs[3].x, qs1); qs1 = fmaf(xs[3].y, xs[3].y, qs1);
#pragma unroll
        for (int i = 0; i < 4; i++)
            qh[c][i] = h2u(__floats2half2_rn(xs[i].x * L2E, xs[i].y * L2E));
    }
    qs0 += __shfl_xor_sync(0xffffffffu, qs0, 1);
    qs0 += __shfl_xor_sync(0xffffffffu, qs0, 2);
    qs1 += __shfl_xor_sync(0xffffffffu, qs1, 1);
    qs1 += __shfl_xor_sync(0xffffffffu, qs1, 2);

    // static per-row bound (log2 domain): p = 2^(s - m) <= 2^15.02 < fp16 max
    const float kmax2 = __int_as_float(g_KmaxI[h]);
    const float m0c = sqrtf(qs0 * kmax2) * L2E - 15.0f;
    const float m1c = sqrtf(qs1 * kmax2) * L2E - 15.0f;

    float lacc[4] = {0.f, 0.f, 0.f, 0.f};   // ones-MMA accumulator: lacc[0]=l(row grp), lacc[2]=l(row grp+8)
    float o[16][4];
#pragma unroll
    for (int n = 0; n < 16; n++)
#pragma unroll
        for (int j = 0; j < 4; j++) o[n][j] = 0.f;

    auto fill = [&](int stage, int k0) {
        unsigned sbase = smem_base + (unsigned)(stage * STG_SIZE * 2);
#pragma unroll
        for (int it = 0; it < 4; it++) {
            int c   = it * 128 + tid;
            int key = c >> 2;
            int ch  = c & 3;
            const __half* src = g_Kh + (size_t)(k0 + key) * ZIPD + h * DH + ch * 8;
            unsigned dst = sbase + (unsigned)((key * KSTR + ch * 8) * 2);
            CP16(dst, src);
        }
#pragma unroll
        for (int it = 0; it < 16; it++) {
            int c   = it * 128 + tid;
            int row = c >> 4;
            int col = c & 15;
            const __half* src = g_V + (size_t)(k0 + row) * DMODEL + h * DV + col * 8;
            unsigned dst = sbase + (unsigned)((STG_V + row * VSTR2 + col * 8) * 2);
            CP16(dst, src);
        }
    };

    fill(0, 0);
    asm volatile("cp.async.commit_group;");

    for (int kt = 0; kt < NTILE; kt++) {
        asm volatile("cp.async.wait_group 0;");
        __syncthreads();
        if (kt + 1 < NTILE) {
            fill((kt + 1) & 1, (kt + 1) * 128);
            asm volatile("cp.async.commit_group;");
        }

        const unsigned sb   = smem_base + (unsigned)((kt & 1) * STG_SIZE * 2);
        const unsigned sbKh = sb;
        const unsigned sbV  = sb + STG_V * 2;

        // ---- S = Q K^T over 128 keys (log2 domain) ----
        float sc[2][8][4];
#pragma unroll
        for (int s2 = 0; s2 < 2; s2++)
#pragma unroll
            for (int nb = 0; nb < 8; nb++)
#pragma unroll
                for (int j = 0; j < 4; j++) sc[s2][nb][j] = 0.f;

#pragma unroll
        for (int s2 = 0; s2 < 2; s2++)
#pragma unroll
            for (int nb = 0; nb < 8; nb++) {
                unsigned bh[4];
                LDSM4(bh[0], bh[1], bh[2], bh[3],
                      sbKh + (unsigned)(((s2 * 64 + nb * 8) * KSTR) * 2) + k_lofs);
#pragma unroll
                for (int c = 0; c < 2; c++)
                    mma16816(sc[s2][nb][0], sc[s2][nb][1], sc[s2][nb][2], sc[s2][nb][3],
                             qh[c][0], qh[c][1], qh[c][2], qh[c][3], bh[2 * c], bh[2 * c + 1]);
            }

        // ---- p = 2^(s - m): fp32 subtract, pack, f16x2 exp (results ARE the A-frags) ----
        unsigned pa[2][8][2];
#pragma unroll
        for (int s2 = 0; s2 < 2; s2++)
#pragma unroll
            for (int nb = 0; nb < 8; nb++) {
                __half2 e0 = __floats2half2_rn(sc[s2][nb][0] - m0c, sc[s2][nb][1] - m0c);
                __half2 e1 = __floats2half2_rn(sc[s2][nb][2] - m1c, sc[s2][nb][3] - m1c);
                pa[s2][nb][0] = h2u(h2exp2(e0));
                pa[s2][nb][1] = h2u(h2exp2(e1));
            }

        // ---- O += P V; l via ones-MMA (sums the exact fp16 p used by PV) ----
#pragma unroll
        for (int s2 = 0; s2 < 2; s2++)
#pragma unroll
            for (int j = 0; j < 4; j++) {
                unsigned a0 = pa[s2][2 * j][0],     a1 = pa[s2][2 * j][1];
                unsigned a2 = pa[s2][2 * j + 1][0], a3 = pa[s2][2 * j + 1][1];
                mma16816(lacc[0], lacc[1], lacc[2], lacc[3], a0, a1, a2, a3, ONES, ONES);
#pragma unroll
                for (int p = 0; p < 8; p++) {
                    unsigned bv[4];
                    LDSM4T(bv[0], bv[1], bv[2], bv[3],
                           sbV + (unsigned)((((s2 * 64 + j * 16) * VSTR2) + p * 16) * 2) + v_lofs);
                    mma16816(o[2 * p][0], o[2 * p][1], o[2 * p][2], o[2 * p][3],
                             a0, a1, a2, a3, bv[0], bv[1]);
                    mma16816(o[2 * p + 1][0], o[2 * p + 1][1], o[2 * p + 1][2], o[2 * p + 1][3],
                             a0, a1, a2, a3, bv[2], bv[3]);
                }
            }
    }

    // ---- epilogue: l comes straight from the ones-MMA accumulator ----
    float inv0 = 1.f / lacc[0], inv1 = 1.f / lacc[2];
    int row0 = qr + grp, row1 = qr + grp + 8;
#pragma unroll
    for (int p = 0; p < 16; p++) {
        int col = h * DV + p * 8 + 2 * t;
        *(float2*)(O + (size_t)row0 * DMODEL + col) = make_float2(o[p][0] * inv0, o[p][1] * inv0);
        *(float2*)(O + (size_t)row1 * DMODEL + col) = make_float2(o[p][2] * inv1, o[p][3] * inv1);
    }
}

// ---------------- launch ----------------
extern "C" void kernel_launch(void* const* d_in, const int* in_sizes, int n_in,
                              void* d_out, int out_size)
{
    const float* q   = (const float*)d_in[0];
    const float* k   = (const float*)d_in[1];
    const float* v   = (const float*)d_in[2];
    const float* wq  = (const float*)d_in[3];
    const float* bq  = (const float*)d_in[4];
    const float* wk  = (const float*)d_in[5];
    const float* bk  = (const float*)d_in[6];
    const float* wvr = (const float*)d_in[7];
    const float* bvr = (const float*)d_in[8];
    const float* wvl = (const float*)d_in[9];
    const float* bvl = (const float*)d_in[10];
    float* out = (float*)d_out;

    conv_w_kernel<<<(4 * ZIPD * DMODEL / 4) / 256, 256>>>(wq, wk, wvr, wvl);

    const int GEMM_SMEM = 2 * G_STG * (int)sizeof(__half);   // 61440 B
    cudaFuncSetAttribute(gemm1_kernel, cudaFuncAttributeMaxDynamicSharedMemorySize, GEMM_SMEM);
    cudaFuncSetAttribute(gemm2_kernel, cudaFuncAttributeMaxDynamicSharedMemorySize, GEMM_SMEM);

    gemm1_kernel<<<dim3(ZIPD / 64, SEQ / 128, 3), 128, GEMM_SMEM>>>(q, k, v, bq, bk, bvr);

    knorm_kernel<<<dim3(SEQ / 256, HEADS), 256>>>();   // needs g_Kh (gemm1); idempotent atomicMax

    gemm2_kernel<<<dim3(DMODEL / 64, SEQ / 128, 1), 128, GEMM_SMEM>>>(bvl);

    const int ATTN_SMEM = NSTAGE * STG_SIZE * (int)sizeof(__half);   // 90112 B
    cudaFuncSetAttribute(attn_kernel, cudaFuncAttributeMaxDynamicSharedMemorySize, ATTN_SMEM);
    attn_kernel<<<dim3(SEQ / 64, HEADS), 128, ATTN_SMEM>>>(out);
}